// round 5
// baseline (speedup 1.0000x reference)
#include <cuda_runtime.h>
#include <math.h>

#define LQ    1024
#define CD    256
#define NH    8
#define NL    4
#define NLOG  272          // 16 deform + 256 add-key logits
#define SEG   528          // 256 kw + 256 attn_add + 1 sa + 15 pad (stays zero)
#define KTOT  (NH*SEG)     // 4224
#define KH0   272          // k_fused half 0 (17 tiles)
#define KH1   256          // k_fused half 1 (16 tiles)

typedef unsigned long long ull;

__device__ __forceinline__ ull f2fma(ull a, ull b, ull c) {
    ull d; asm("fma.rn.f32x2 %0, %1, %2, %3;" : "=l"(d) : "l"(a), "l"(b), "l"(c)); return d;
}
__device__ __forceinline__ ull splat2(float x) {
    ull d; asm("mov.b64 %0, {%1, %1};" : "=l"(d) : "f"(x)); return d;
}
__device__ __forceinline__ void unpack2(ull v, float& lo, float& hi) {
    asm("mov.b64 {%0, %1}, %2;" : "=f"(lo), "=f"(hi) : "l"(v));
}
__device__ __forceinline__ void cpasync16(unsigned s, const void* g) {
    asm volatile("cp.async.cg.shared.global [%0], [%1], 16;" :: "r"(s), "l"(g));
}
#define CP_COMMIT() asm volatile("cp.async.commit_group;" ::: "memory")
#define CP_WAIT0()  asm volatile("cp.async.wait_group 0;" ::: "memory")

// ---------------- scratch (device globals; zero-initialized) ----------------
__device__ __align__(16) float g_hw[9*CD];
__device__ __align__(16) float g_off[LQ*CD];
__device__ __align__(16) int   g_fidx[NH*16*LQ];
__device__ __align__(16) float g_T[NH*NL*LQ*CD];
__device__ __align__(16) float g_logits[NH*NLOG*LQ];
__device__ __align__(16) float g_A2[NH*CD*CD];
__device__ __align__(16) float g_v2[NH*CD*CD];
__device__ __align__(16) float g_A[LQ*KTOT];
__device__ __align__(16) float g_B[KTOT*CD];
__device__ __align__(16) float g_Cpart[NH*2*LQ*CD];

// ---------------- 64x256 block GEMM, K multiple of 16 ----------------
// MODE 0: C[i][j] = sum_k A[i][k]*B[j][k]   (B row-major [256][K], NT; reg prefetch)
// MODE 1: C[i][j] = sum_k A[i][k]*B[k][j]   (B row-major [K][256], NN; cp.async)
// MODE 2: like 1 but B row k is IF + gidx[k]*256 (gathered; cp.async)
template<int MODE>
__device__ __forceinline__ void gemm_64x256(
    const float* __restrict__ A, int a_row_stride,
    const float* __restrict__ B, int ldb,
    const int* __restrict__ gidx, const float* __restrict__ IF,
    int K,
    float* __restrict__ C, int c_row_stride,
    const float* __restrict__ bias)
{
    __shared__ float As[2][16][64];
    __shared__ float Bs[2][16][264];
    const int tid  = threadIdx.x;
    const int mrow = (tid >> 5) << 3;
    const int ncol = (tid & 31) << 3;
    ull acc[8][4];
#pragma unroll
    for (int i = 0; i < 8; i++)
#pragma unroll
        for (int j = 0; j < 4; j++) acc[i][j] = 0ull;

    const int ar = tid >> 2, ac = (tid & 3) << 2;
    // cp.async mapping (MODE 1/2): thread t copies 4 x 16B of row (t>>4)
    const int brow = tid >> 4, bcol = (tid & 15) << 2;   // bcol in floats
    unsigned bs_sm[2];
    bs_sm[0] = (unsigned)__cvta_generic_to_shared(&Bs[0][brow][bcol]);
    bs_sm[1] = (unsigned)__cvta_generic_to_shared(&Bs[1][brow][bcol]);
    // MODE 0 mapping
    const int kk0 = tid >> 4, j00 = (tid & 15) << 4;

    float4 pa, pb0, pb1, pb2, pb3;

    // ---- prologue: tile 0 ----
    pa = *(const float4*)(A + (size_t)ar * a_row_stride + ac);
    if (MODE == 0) {
        const float* br = B + (size_t)tid * ldb;
        pb0 = ((const float4*)br)[0]; pb1 = ((const float4*)br)[1];
        pb2 = ((const float4*)br)[2]; pb3 = ((const float4*)br)[3];
        Bs[0][0][tid]  = pb0.x; Bs[0][1][tid]  = pb0.y; Bs[0][2][tid]  = pb0.z; Bs[0][3][tid]  = pb0.w;
        Bs[0][4][tid]  = pb1.x; Bs[0][5][tid]  = pb1.y; Bs[0][6][tid]  = pb1.z; Bs[0][7][tid]  = pb1.w;
        Bs[0][8][tid]  = pb2.x; Bs[0][9][tid]  = pb2.y; Bs[0][10][tid] = pb2.z; Bs[0][11][tid] = pb2.w;
        Bs[0][12][tid] = pb3.x; Bs[0][13][tid] = pb3.y; Bs[0][14][tid] = pb3.z; Bs[0][15][tid] = pb3.w;
    } else {
        const float* br = (MODE == 2) ? (IF + (size_t)gidx[brow] * CD)
                                      : (B + (size_t)brow * ldb);
#pragma unroll
        for (int i = 0; i < 4; i++)
            cpasync16(bs_sm[0] + i * 256, br + bcol + i * 64);
        CP_COMMIT();
        CP_WAIT0();
    }
    As[0][ac + 0][ar] = pa.x; As[0][ac + 1][ar] = pa.y;
    As[0][ac + 2][ar] = pa.z; As[0][ac + 3][ar] = pa.w;
    __syncthreads();

    int buf = 0;
    for (int k0 = 16;; k0 += 16) {
        const bool more = (k0 < K);
        const int nb = buf ^ 1;
        if (more) {
            pa = *(const float4*)(A + (size_t)ar * a_row_stride + k0 + ac);
            if (MODE == 0) {
                const float* br = B + (size_t)tid * ldb + k0;
                pb0 = ((const float4*)br)[0]; pb1 = ((const float4*)br)[1];
                pb2 = ((const float4*)br)[2]; pb3 = ((const float4*)br)[3];
            } else {
                const float* br = (MODE == 2) ? (IF + (size_t)gidx[k0 + brow] * CD)
                                              : (B + (size_t)(k0 + brow) * ldb);
#pragma unroll
                for (int i = 0; i < 4; i++)
                    cpasync16(bs_sm[nb] + i * 256, br + bcol + i * 64);
                CP_COMMIT();
            }
        }
#pragma unroll
        for (int k = 0; k < 16; k++) {
            float4 av0 = *(const float4*)&As[buf][k][mrow];
            float4 av1 = *(const float4*)&As[buf][k][mrow + 4];
            const ull* bp = (const ull*)&Bs[buf][k][ncol];
            ull b0 = bp[0], b1 = bp[1], b2 = bp[2], b3 = bp[3];
            float a8[8] = {av0.x, av0.y, av0.z, av0.w, av1.x, av1.y, av1.z, av1.w};
#pragma unroll
            for (int i = 0; i < 8; i++) {
                ull as = splat2(a8[i]);
                acc[i][0] = f2fma(as, b0, acc[i][0]);
                acc[i][1] = f2fma(as, b1, acc[i][1]);
                acc[i][2] = f2fma(as, b2, acc[i][2]);
                acc[i][3] = f2fma(as, b3, acc[i][3]);
            }
        }
        if (!more) break;
        As[nb][ac + 0][ar] = pa.x; As[nb][ac + 1][ar] = pa.y;
        As[nb][ac + 2][ar] = pa.z; As[nb][ac + 3][ar] = pa.w;
        if (MODE == 0) {
            Bs[nb][0][tid]  = pb0.x; Bs[nb][1][tid]  = pb0.y; Bs[nb][2][tid]  = pb0.z; Bs[nb][3][tid]  = pb0.w;
            Bs[nb][4][tid]  = pb1.x; Bs[nb][5][tid]  = pb1.y; Bs[nb][6][tid]  = pb1.z; Bs[nb][7][tid]  = pb1.w;
            Bs[nb][8][tid]  = pb2.x; Bs[nb][9][tid]  = pb2.y; Bs[nb][10][tid] = pb2.z; Bs[nb][11][tid] = pb2.w;
            Bs[nb][12][tid] = pb3.x; Bs[nb][13][tid] = pb3.y; Bs[nb][14][tid] = pb3.z; Bs[nb][15][tid] = pb3.w;
        } else {
            CP_WAIT0();
        }
        __syncthreads();
        buf = nb;
    }

#pragma unroll
    for (int i = 0; i < 8; i++) {
        float o[8];
#pragma unroll
        for (int jj = 0; jj < 4; jj++) unpack2(acc[i][jj], o[2*jj], o[2*jj+1]);
        if (bias) {
#pragma unroll
            for (int j = 0; j < 8; j++) o[j] += bias[ncol + j];
        }
        float* cr = C + (size_t)(mrow + i) * c_row_stride + ncol;
        *(float4*)(cr + 0) = *(const float4*)(o + 0);
        *(float4*)(cr + 4) = *(const float4*)(o + 4);
    }
}

// ---------------- kernels ----------------

// L1: head-mix softmax (block 16) + off = q @ W_off.T + b_off (blocks 0..15)
__global__ void __launch_bounds__(256, 2) k_off_hw(const float* __restrict__ q,
                                                   const float* __restrict__ Woff,
                                                   const float* __restrict__ boff,
                                                   const float* __restrict__ Wmix) {
    if (blockIdx.x == 16) {
        int c = threadIdx.x;
        float v[9], m = -1e30f;
#pragma unroll
        for (int j = 0; j < 9; j++) { v[j] = Wmix[c * 9 + j]; m = fmaxf(m, v[j]); }
        float s = 0.f;
#pragma unroll
        for (int j = 0; j < 9; j++) { v[j] = expf(v[j] - m); s += v[j]; }
        float inv = 1.f / s;
#pragma unroll
        for (int j = 0; j < 9; j++) g_hw[j * CD + c] = v[j] * inv;
        return;
    }
    gemm_64x256<0>(q + (size_t)blockIdx.x * 64 * CD, CD, Woff, CD, nullptr, nullptr,
                   CD, g_off + (size_t)blockIdx.x * 64 * CD, CD, boff);
}

__global__ void __launch_bounds__(256) k_idx(const float* __restrict__ refp,
                                             const int* __restrict__ iss,
                                             const int* __restrict__ lstart) {
    int gid = blockIdx.x * 256 + threadIdx.x;    // 1024*128
    int lq = gid >> 7, r2 = gid & 127;
    int l = (r2 >> 2) & 3;
    float2 off = *(const float2*)(g_off + (size_t)lq * CD + r2 * 2);
    float2 rp  = *(const float2*)(refp + ((size_t)lq * NL + l) * 2);
    int H = iss[l * 2], W = iss[l * 2 + 1];
    float loc0 = rp.x + off.x / (float)W;   // wh = [W, H]
    float loc1 = rp.y + off.y / (float)H;
    loc0 = fminf(fmaxf(loc0, 0.f), 0.999f);
    loc1 = fminf(fmaxf(loc1, 0.f), 0.999f);
    int i0 = (int)(loc0 * (float)H);        // idx = loc * [H, W]
    int i1 = (int)(loc1 * (float)W);
    int flat = i0 + i1 * H + lstart[l];
    g_fidx[(size_t)r2 * LQ + lq] = flat;    // r2 = h*16 + l*4 + p
}

// L3: blocks [0,512): T GEMMs ; blocks [512,576): A2/v2 GEMMs
__global__ void __launch_bounds__(256, 2) k_T_a2v2(const float* __restrict__ q,
                                                   const float* __restrict__ IF,
                                                   const float* __restrict__ addk,
                                                   const float* __restrict__ Wattn,
                                                   const float* __restrict__ Wval,
                                                   const float* __restrict__ bval) {
    if (blockIdx.x < 512) {
        int hl = blockIdx.x >> 4, rcl = blockIdx.x & 15;
        gemm_64x256<2>(q + (size_t)rcl * CD, 16 * CD, nullptr, 0,
                       g_fidx + hl * 4096 + rcl * 256, IF, 256,
                       g_T + ((size_t)hl * LQ + rcl) * CD, 16 * CD, nullptr);
    } else {
        int b = blockIdx.x - 512;
        int mat = b >> 2, mt = b & 3;
        const float* A = addk + (size_t)mt * 64 * CD;
        if (mat < 8) {
            gemm_64x256<0>(A, CD, Wattn + (size_t)(mat * 4 + 4) * CD * CD, CD, nullptr, nullptr,
                           CD, g_A2 + (size_t)mat * CD * CD + mt * 64 * CD, CD, nullptr);
        } else {
            int h = mat - 8;
            gemm_64x256<0>(A, CD, Wval + (size_t)(2 * h + 1) * CD * CD, CD, nullptr, nullptr,
                           CD, g_v2 + (size_t)h * CD * CD + mt * 64 * CD, CD, bval + (2 * h + 1) * CD);
        }
    }
}

// L4: blocks [0,256): deform logits ; blocks [256,384): add-key logits
__global__ void __launch_bounds__(256, 2) k_logits(const float* __restrict__ Wattn,
                                                   const float* __restrict__ q) {
    if (blockIdx.x < 256) {
        int hl = blockIdx.x >> 3, chunk = blockIdx.x & 7;
        int h = hl >> 2, l = hl & 3;
        for (int it = threadIdx.x; it < 512; it += 256) {
            int p = it >> 7;
            int lq = chunk * 128 + (it & 127);
            int r = p * 64 + (lq >> 4);
            const float4* srow = (const float4*)(Wattn + (size_t)hl * CD * CD + (size_t)r * CD);
            const float4* trow = (const float4*)(g_T + ((size_t)hl * LQ + lq) * CD);
            float s0 = 0.f, s1 = 0.f, s2 = 0.f, s3 = 0.f;
#pragma unroll
            for (int d = 0; d < 64; d++) {
                float4 a = srow[d]; float4 b = trow[d];
                s0 = fmaf(a.x, b.x, s0); s1 = fmaf(a.y, b.y, s1);
                s2 = fmaf(a.z, b.z, s2); s3 = fmaf(a.w, b.w, s3);
            }
            g_logits[(size_t)h * NLOG * LQ + (size_t)(l * 4 + p) * LQ + lq] = (s0 + s1) + (s2 + s3);
        }
    } else {
        int b = blockIdx.x - 256;
        int h = b >> 4, mt = (b >> 2) & 3, nt = b & 3;
        gemm_64x256<0>(g_A2 + (size_t)h * CD * CD + mt * 64 * CD, CD,
                       q + (size_t)nt * 256 * CD, CD, nullptr, nullptr, CD,
                       g_logits + (size_t)h * NLOG * LQ + (size_t)(16 + mt * 64) * LQ + nt * 256,
                       LQ, nullptr);
    }
}

__global__ void __launch_bounds__(256) k_softmax() {
    int warp = threadIdx.x >> 5, lane = threadIdx.x & 31;
    int col = blockIdx.x * 8 + warp;            // 8192 total
    int h = col >> 10, lq = col & 1023;
    float* base = g_logits + (size_t)h * NLOG * LQ + lq;
    float v[9];
    float vmax = -1e30f;
#pragma unroll
    for (int k = 0; k < 9; k++) {
        int s = lane + 32 * k;
        v[k] = (s < NLOG) ? base[(size_t)s * LQ] : -1e30f;
        vmax = fmaxf(vmax, v[k]);
    }
#pragma unroll
    for (int o = 16; o > 0; o >>= 1) vmax = fmaxf(vmax, __shfl_xor_sync(0xffffffffu, vmax, o));
    float sum = 0.f;
#pragma unroll
    for (int k = 0; k < 9; k++) {
        int s = lane + 32 * k;
        v[k] = (s < NLOG) ? expf(v[k] - vmax) : 0.f;
        sum += v[k];
    }
#pragma unroll
    for (int o = 16; o > 0; o >>= 1) sum += __shfl_xor_sync(0xffffffffu, sum, o);
    float inv = 1.f / sum;
    float* arow = g_A + (size_t)lq * KTOT + h * SEG;
    float sa = 0.f;
#pragma unroll
    for (int k = 0; k < 9; k++) {
        int s = lane + 32 * k;
        if (s >= NLOG) continue;
        float w = v[k] * inv;
        if (s < 16) { base[(size_t)s * LQ] = w; sa += w; }
        else        arow[256 + s - 16] = w;
    }
#pragma unroll
    for (int o = 16; o > 0; o >>= 1) sa += __shfl_xor_sync(0xffffffffu, sa, o);
    if (lane == 0) arow[512] = sa;
}

// L6: blocks [0,128): kw gather ; blocks [128, 128+KTOT): B-matrix prep
__global__ void __launch_bounds__(256) k_kw_bprep(const float* __restrict__ IF,
                                                  const float* __restrict__ Wval,
                                                  const float* __restrict__ bval) {
    if (blockIdx.x < 128) {
        int h = blockIdx.x >> 4, qb = blockIdx.x & 15;
        int lq0 = qb * 64;
        __shared__ float ws[16][64];
        __shared__ int   is[16][64];
        int tid = threadIdx.x;
        for (int i = tid; i < 1024; i += 256) {
            int s = i >> 6, qq = i & 63;
            ws[s][qq] = g_logits[(size_t)h * NLOG * LQ + (size_t)s * LQ + lq0 + qq];
            is[s][qq] = g_fidx[(h * 16 + s) * LQ + lq0 + qq];
        }
        __syncthreads();
        int qi = tid >> 2, dc = (tid & 3) << 6;
        float4 acc[16];
#pragma unroll
        for (int r = 0; r < 16; r++) acc[r] = make_float4(0.f, 0.f, 0.f, 0.f);
        for (int s = 0; s < 16; s++) {
            float w = ws[s][qi];
            const float4* row = (const float4*)(IF + (size_t)is[s][qi] * CD + dc);
#pragma unroll
            for (int r = 0; r < 16; r++) {
                float4 kv = row[r];
                acc[r].x = fmaf(w, kv.x, acc[r].x);
                acc[r].y = fmaf(w, kv.y, acc[r].y);
                acc[r].z = fmaf(w, kv.z, acc[r].z);
                acc[r].w = fmaf(w, kv.w, acc[r].w);
            }
        }
        float4* out = (float4*)(g_A + (size_t)(lq0 + qi) * KTOT + h * SEG + dc);
#pragma unroll
        for (int r = 0; r < 16; r++) out[r] = acc[r];
    } else {
        int k = blockIdx.x - 128;           // 0..KTOT-1
        int c = threadIdx.x;
        int h = k / SEG, r = k - h * SEG;
        float hw = g_hw[h * CD + c];
        float val;
        if (r < 256)       val = hw * Wval[((size_t)(2 * h) * CD + c) * CD + r];
        else if (r < 512)  val = hw * g_v2[((size_t)h * CD + (r - 256)) * CD + c];
        else if (r == 512) val = hw * bval[(2 * h) * CD + c];
        else               val = 0.f;
        g_B[(size_t)k * CD + c] = val;
    }
}

// fused output GEMM per (head, K-half) -> per-(head,half) partials
__global__ void __launch_bounds__(256, 2) k_fused() {
    int h = blockIdx.x >> 5;
    int sub = blockIdx.x & 31;
    int mt = sub & 15, half = sub >> 4;
    int koff = half ? KH0 : 0;
    int K    = half ? KH1 : KH0;
    gemm_64x256<1>(g_A + (size_t)mt * 64 * KTOT + h * SEG + koff, KTOT,
                   g_B + ((size_t)h * SEG + koff) * CD, CD, nullptr, nullptr,
                   K,
                   g_Cpart + (((size_t)(h * 2 + half) * LQ) + mt * 64) * CD, CD, nullptr);
}

__global__ void __launch_bounds__(256) k_out(const float* __restrict__ q,
                                             float* __restrict__ out) {
    int e = blockIdx.x * 256 + threadIdx.x;     // 65536 float4
    int c4 = e & 63;
    float4 qv = ((const float4*)q)[e];
    float4 hw = ((const float4*)(g_hw + 8 * CD))[c4];
    float4 r;
    r.x = qv.x * hw.x; r.y = qv.y * hw.y; r.z = qv.z * hw.z; r.w = qv.w * hw.w;
#pragma unroll
    for (int hp = 0; hp < NH * 2; hp++) {
        float4 p = ((const float4*)(g_Cpart + (size_t)hp * LQ * CD))[e];
        r.x += p.x; r.y += p.y; r.z += p.z; r.w += p.w;
    }
    ((float4*)out)[e] = r;
}

extern "C" void kernel_launch(void* const* d_in, const int* in_sizes, int n_in,
                              void* d_out, int out_size) {
    const float* query  = (const float*)d_in[0];
    const float* refp   = (const float*)d_in[1];
    const float* IF     = (const float*)d_in[2];
    const int*   iss    = (const int*)d_in[3];
    const float* addk   = (const float*)d_in[4];
    const int*   lstart = (const int*)d_in[5];
    const float* Woff   = (const float*)d_in[6];
    const float* boff   = (const float*)d_in[7];
    const float* Wattn  = (const float*)d_in[8];
    const float* Wval   = (const float*)d_in[9];
    const float* bval   = (const float*)d_in[10];
    const float* Wmix   = (const float*)d_in[11];
    float* out = (float*)d_out;

    k_off_hw<<<17, 256>>>(query, Woff, boff, Wmix);
    k_idx<<<512, 256>>>(refp, iss, lstart);
    k_T_a2v2<<<576, 256>>>(query, IF, addk, Wattn, Wval, bval);
    k_logits<<<384, 256>>>(Wattn, query);
    k_softmax<<<1024, 256>>>();
    k_kw_bprep<<<128 + KTOT, 256>>>(IF, Wval, bval);
    k_fused<<<256, 256>>>();
    k_out<<<256, 256>>>(query, out);
}

// round 6
// speedup vs baseline: 1.0023x; 1.0023x over previous
#include <cuda_runtime.h>
#include <math.h>

#define LQ    1024
#define CD    256
#define NH    8
#define NL    4
#define NLOG  272          // 16 deform + 256 add-key logits
#define SEG   528          // 256 kw + 256 attn_add + 1 sa + 15 pad (stays zero)
#define KTOT  (NH*SEG)     // 4224
#define KH0   272          // k_fused half 0 (17 tiles)
#define KH1   256          // k_fused half 1 (16 tiles)

typedef unsigned long long ull;

__device__ __forceinline__ ull f2fma(ull a, ull b, ull c) {
    ull d; asm("fma.rn.f32x2 %0, %1, %2, %3;" : "=l"(d) : "l"(a), "l"(b), "l"(c)); return d;
}
__device__ __forceinline__ ull splat2(float x) {
    ull d; asm("mov.b64 %0, {%1, %1};" : "=l"(d) : "f"(x)); return d;
}
__device__ __forceinline__ void unpack2(ull v, float& lo, float& hi) {
    asm("mov.b64 {%0, %1}, %2;" : "=f"(lo), "=f"(hi) : "l"(v));
}
__device__ __forceinline__ void cpasync16(unsigned s, const void* g) {
    asm volatile("cp.async.cg.shared.global [%0], [%1], 16;" :: "r"(s), "l"(g));
}
#define CP_COMMIT() asm volatile("cp.async.commit_group;" ::: "memory")
#define CP_WAIT0()  asm volatile("cp.async.wait_group 0;" ::: "memory")

// ---------------- scratch (device globals; zero-initialized) ----------------
__device__ __align__(16) float g_hw[9*CD];
__device__ __align__(16) float g_off[LQ*CD];
__device__ __align__(16) int   g_fidx[NH*16*LQ];
__device__ __align__(16) float g_T[NH*NL*LQ*CD];
__device__ __align__(16) float g_logits[NH*NLOG*LQ];
__device__ __align__(16) float g_A2[NH*CD*CD];
__device__ __align__(16) float g_v2[NH*CD*CD];
__device__ __align__(16) float g_A[LQ*KTOT];
__device__ __align__(16) float g_B[KTOT*CD];
__device__ __align__(16) float g_Cpart[NH*2*LQ*CD];

// ---------------- 64x256 block GEMM, K multiple of 16 ----------------
// MODE 0: C[i][j] = sum_k A[i][k]*B[j][k]   (B row-major [256][K], NT; reg prefetch)
// MODE 1: C[i][j] = sum_k A[i][k]*B[k][j]   (B row-major [K][256], NN; cp.async)
// MODE 2: like 1 but B row k is IF + gidx[k]*256 (gathered; cp.async)
template<int MODE>
__device__ __forceinline__ void gemm_64x256(
    const float* __restrict__ A, int a_row_stride,
    const float* __restrict__ B, int ldb,
    const int* __restrict__ gidx, const float* __restrict__ IF,
    int K,
    float* __restrict__ C, int c_row_stride,
    const float* __restrict__ bias)
{
    __shared__ float As[2][16][64];
    __shared__ float Bs[2][16][264];
    const int tid  = threadIdx.x;
    const int mrow = (tid >> 5) << 3;
    const int ncol = (tid & 31) << 3;
    ull acc[8][4];
#pragma unroll
    for (int i = 0; i < 8; i++)
#pragma unroll
        for (int j = 0; j < 4; j++) acc[i][j] = 0ull;

    const int ar = tid >> 2, ac = (tid & 3) << 2;
    // cp.async mapping (MODE 1/2): thread t copies 4 x 16B of row (t>>4)
    const int brow = tid >> 4, bcol = (tid & 15) << 2;   // bcol in floats
    unsigned bs_sm[2];
    bs_sm[0] = (unsigned)__cvta_generic_to_shared(&Bs[0][brow][bcol]);
    bs_sm[1] = (unsigned)__cvta_generic_to_shared(&Bs[1][brow][bcol]);
    // MODE 0 mapping
    const int kk0 = tid >> 4, j00 = (tid & 15) << 4;

    float4 pa, pb0, pb1, pb2, pb3;

    // ---- prologue: tile 0 ----
    pa = *(const float4*)(A + (size_t)ar * a_row_stride + ac);
    if (MODE == 0) {
        const float* br = B + (size_t)tid * ldb;
        pb0 = ((const float4*)br)[0]; pb1 = ((const float4*)br)[1];
        pb2 = ((const float4*)br)[2]; pb3 = ((const float4*)br)[3];
        Bs[0][0][tid]  = pb0.x; Bs[0][1][tid]  = pb0.y; Bs[0][2][tid]  = pb0.z; Bs[0][3][tid]  = pb0.w;
        Bs[0][4][tid]  = pb1.x; Bs[0][5][tid]  = pb1.y; Bs[0][6][tid]  = pb1.z; Bs[0][7][tid]  = pb1.w;
        Bs[0][8][tid]  = pb2.x; Bs[0][9][tid]  = pb2.y; Bs[0][10][tid] = pb2.z; Bs[0][11][tid] = pb2.w;
        Bs[0][12][tid] = pb3.x; Bs[0][13][tid] = pb3.y; Bs[0][14][tid] = pb3.z; Bs[0][15][tid] = pb3.w;
    } else {
        const float* br = (MODE == 2) ? (IF + (size_t)gidx[brow] * CD)
                                      : (B + (size_t)brow * ldb);
#pragma unroll
        for (int i = 0; i < 4; i++)
            cpasync16(bs_sm[0] + i * 256, br + bcol + i * 64);
        CP_COMMIT();
        CP_WAIT0();
    }
    As[0][ac + 0][ar] = pa.x; As[0][ac + 1][ar] = pa.y;
    As[0][ac + 2][ar] = pa.z; As[0][ac + 3][ar] = pa.w;
    __syncthreads();

    int buf = 0;
    for (int k0 = 16;; k0 += 16) {
        const bool more = (k0 < K);
        const int nb = buf ^ 1;
        if (more) {
            pa = *(const float4*)(A + (size_t)ar * a_row_stride + k0 + ac);
            if (MODE == 0) {
                const float* br = B + (size_t)tid * ldb + k0;
                pb0 = ((const float4*)br)[0]; pb1 = ((const float4*)br)[1];
                pb2 = ((const float4*)br)[2]; pb3 = ((const float4*)br)[3];
            } else {
                const float* br = (MODE == 2) ? (IF + (size_t)gidx[k0 + brow] * CD)
                                              : (B + (size_t)(k0 + brow) * ldb);
#pragma unroll
                for (int i = 0; i < 4; i++)
                    cpasync16(bs_sm[nb] + i * 256, br + bcol + i * 64);
                CP_COMMIT();
            }
        }
#pragma unroll
        for (int k = 0; k < 16; k++) {
            float4 av0 = *(const float4*)&As[buf][k][mrow];
            float4 av1 = *(const float4*)&As[buf][k][mrow + 4];
            const ull* bp = (const ull*)&Bs[buf][k][ncol];
            ull b0 = bp[0], b1 = bp[1], b2 = bp[2], b3 = bp[3];
            float a8[8] = {av0.x, av0.y, av0.z, av0.w, av1.x, av1.y, av1.z, av1.w};
#pragma unroll
            for (int i = 0; i < 8; i++) {
                ull as = splat2(a8[i]);
                acc[i][0] = f2fma(as, b0, acc[i][0]);
                acc[i][1] = f2fma(as, b1, acc[i][1]);
                acc[i][2] = f2fma(as, b2, acc[i][2]);
                acc[i][3] = f2fma(as, b3, acc[i][3]);
            }
        }
        if (!more) break;
        As[nb][ac + 0][ar] = pa.x; As[nb][ac + 1][ar] = pa.y;
        As[nb][ac + 2][ar] = pa.z; As[nb][ac + 3][ar] = pa.w;
        if (MODE == 0) {
            Bs[nb][0][tid]  = pb0.x; Bs[nb][1][tid]  = pb0.y; Bs[nb][2][tid]  = pb0.z; Bs[nb][3][tid]  = pb0.w;
            Bs[nb][4][tid]  = pb1.x; Bs[nb][5][tid]  = pb1.y; Bs[nb][6][tid]  = pb1.z; Bs[nb][7][tid]  = pb1.w;
            Bs[nb][8][tid]  = pb2.x; Bs[nb][9][tid]  = pb2.y; Bs[nb][10][tid] = pb2.z; Bs[nb][11][tid] = pb2.w;
            Bs[nb][12][tid] = pb3.x; Bs[nb][13][tid] = pb3.y; Bs[nb][14][tid] = pb3.z; Bs[nb][15][tid] = pb3.w;
        } else {
            CP_WAIT0();
        }
        __syncthreads();
        buf = nb;
    }

#pragma unroll
    for (int i = 0; i < 8; i++) {
        float o[8];
#pragma unroll
        for (int jj = 0; jj < 4; jj++) unpack2(acc[i][jj], o[2*jj], o[2*jj+1]);
        if (bias) {
#pragma unroll
            for (int j = 0; j < 8; j++) o[j] += bias[ncol + j];
        }
        float* cr = C + (size_t)(mrow + i) * c_row_stride + ncol;
        *(float4*)(cr + 0) = *(const float4*)(o + 0);
        *(float4*)(cr + 4) = *(const float4*)(o + 4);
    }
}

// ---------------- kernels ----------------

// L1: head-mix softmax (block 16) + off = q @ W_off.T + b_off (blocks 0..15)
__global__ void __launch_bounds__(256, 2) k_off_hw(const float* __restrict__ q,
                                                   const float* __restrict__ Woff,
                                                   const float* __restrict__ boff,
                                                   const float* __restrict__ Wmix) {
    if (blockIdx.x == 16) {
        int c = threadIdx.x;
        float v[9], m = -1e30f;
#pragma unroll
        for (int j = 0; j < 9; j++) { v[j] = Wmix[c * 9 + j]; m = fmaxf(m, v[j]); }
        float s = 0.f;
#pragma unroll
        for (int j = 0; j < 9; j++) { v[j] = expf(v[j] - m); s += v[j]; }
        float inv = 1.f / s;
#pragma unroll
        for (int j = 0; j < 9; j++) g_hw[j * CD + c] = v[j] * inv;
        return;
    }
    gemm_64x256<0>(q + (size_t)blockIdx.x * 64 * CD, CD, Woff, CD, nullptr, nullptr,
                   CD, g_off + (size_t)blockIdx.x * 64 * CD, CD, boff);
}

__global__ void __launch_bounds__(256) k_idx(const float* __restrict__ refp,
                                             const int* __restrict__ iss,
                                             const int* __restrict__ lstart) {
    int gid = blockIdx.x * 256 + threadIdx.x;    // 1024*128
    int lq = gid >> 7, r2 = gid & 127;
    int l = (r2 >> 2) & 3;
    float2 off = *(const float2*)(g_off + (size_t)lq * CD + r2 * 2);
    float2 rp  = *(const float2*)(refp + ((size_t)lq * NL + l) * 2);
    int H = iss[l * 2], W = iss[l * 2 + 1];
    float loc0 = rp.x + off.x / (float)W;   // wh = [W, H]
    float loc1 = rp.y + off.y / (float)H;
    loc0 = fminf(fmaxf(loc0, 0.f), 0.999f);
    loc1 = fminf(fmaxf(loc1, 0.f), 0.999f);
    int i0 = (int)(loc0 * (float)H);        // idx = loc * [H, W]
    int i1 = (int)(loc1 * (float)W);
    int flat = i0 + i1 * H + lstart[l];
    g_fidx[(size_t)r2 * LQ + lq] = flat;    // r2 = h*16 + l*4 + p
}

// L3: blocks [0,512): T GEMMs ; blocks [512,576): A2/v2 GEMMs
__global__ void __launch_bounds__(256, 2) k_T_a2v2(const float* __restrict__ q,
                                                   const float* __restrict__ IF,
                                                   const float* __restrict__ addk,
                                                   const float* __restrict__ Wattn,
                                                   const float* __restrict__ Wval,
                                                   const float* __restrict__ bval) {
    if (blockIdx.x < 512) {
        int hl = blockIdx.x >> 4, rcl = blockIdx.x & 15;
        gemm_64x256<2>(q + (size_t)rcl * CD, 16 * CD, nullptr, 0,
                       g_fidx + hl * 4096 + rcl * 256, IF, 256,
                       g_T + ((size_t)hl * LQ + rcl) * CD, 16 * CD, nullptr);
    } else {
        int b = blockIdx.x - 512;
        int mat = b >> 2, mt = b & 3;
        const float* A = addk + (size_t)mt * 64 * CD;
        if (mat < 8) {
            gemm_64x256<0>(A, CD, Wattn + (size_t)(mat * 4 + 4) * CD * CD, CD, nullptr, nullptr,
                           CD, g_A2 + (size_t)mat * CD * CD + mt * 64 * CD, CD, nullptr);
        } else {
            int h = mat - 8;
            gemm_64x256<0>(A, CD, Wval + (size_t)(2 * h + 1) * CD * CD, CD, nullptr, nullptr,
                           CD, g_v2 + (size_t)h * CD * CD + mt * 64 * CD, CD, bval + (2 * h + 1) * CD);
        }
    }
}

// L4: blocks [0,256): deform logits ; blocks [256,384): add-key logits
__global__ void __launch_bounds__(256, 2) k_logits(const float* __restrict__ Wattn,
                                                   const float* __restrict__ q) {
    if (blockIdx.x < 256) {
        int hl = blockIdx.x >> 3, chunk = blockIdx.x & 7;
        int h = hl >> 2, l = hl & 3;
        for (int it = threadIdx.x; it < 512; it += 256) {
            int p = it >> 7;
            int lq = chunk * 128 + (it & 127);
            int r = p * 64 + (lq >> 4);
            const float4* srow = (const float4*)(Wattn + (size_t)hl * CD * CD + (size_t)r * CD);
            const float4* trow = (const float4*)(g_T + ((size_t)hl * LQ + lq) * CD);
            float s0 = 0.f, s1 = 0.f, s2 = 0.f, s3 = 0.f;
#pragma unroll
            for (int d = 0; d < 64; d++) {
                float4 a = srow[d]; float4 b = trow[d];
                s0 = fmaf(a.x, b.x, s0); s1 = fmaf(a.y, b.y, s1);
                s2 = fmaf(a.z, b.z, s2); s3 = fmaf(a.w, b.w, s3);
            }
            g_logits[(size_t)h * NLOG * LQ + (size_t)(l * 4 + p) * LQ + lq] = (s0 + s1) + (s2 + s3);
        }
    } else {
        int b = blockIdx.x - 256;
        int h = b >> 4, mt = (b >> 2) & 3, nt = b & 3;
        gemm_64x256<0>(g_A2 + (size_t)h * CD * CD + mt * 64 * CD, CD,
                       q + (size_t)nt * 256 * CD, CD, nullptr, nullptr, CD,
                       g_logits + (size_t)h * NLOG * LQ + (size_t)(16 + mt * 64) * LQ + nt * 256,
                       LQ, nullptr);
    }
}

__global__ void __launch_bounds__(256) k_softmax() {
    int warp = threadIdx.x >> 5, lane = threadIdx.x & 31;
    int col = blockIdx.x * 8 + warp;            // 8192 total
    int h = col >> 10, lq = col & 1023;
    float* base = g_logits + (size_t)h * NLOG * LQ + lq;
    float v[9];
    float vmax = -1e30f;
#pragma unroll
    for (int k = 0; k < 9; k++) {
        int s = lane + 32 * k;
        v[k] = (s < NLOG) ? base[(size_t)s * LQ] : -1e30f;
        vmax = fmaxf(vmax, v[k]);
    }
#pragma unroll
    for (int o = 16; o > 0; o >>= 1) vmax = fmaxf(vmax, __shfl_xor_sync(0xffffffffu, vmax, o));
    float sum = 0.f;
#pragma unroll
    for (int k = 0; k < 9; k++) {
        int s = lane + 32 * k;
        v[k] = (s < NLOG) ? expf(v[k] - vmax) : 0.f;
        sum += v[k];
    }
#pragma unroll
    for (int o = 16; o > 0; o >>= 1) sum += __shfl_xor_sync(0xffffffffu, sum, o);
    float inv = 1.f / sum;
    float* arow = g_A + (size_t)lq * KTOT + h * SEG;
    float sa = 0.f;
#pragma unroll
    for (int k = 0; k < 9; k++) {
        int s = lane + 32 * k;
        if (s >= NLOG) continue;
        float w = v[k] * inv;
        if (s < 16) { base[(size_t)s * LQ] = w; sa += w; }
        else        arow[256 + s - 16] = w;
    }
#pragma unroll
    for (int o = 16; o > 0; o >>= 1) sa += __shfl_xor_sync(0xffffffffu, sa, o);
    if (lane == 0) arow[512] = sa;
}

// L6: blocks [0,128): kw gather ; blocks [128, 128+KTOT): B-matrix prep
__global__ void __launch_bounds__(256) k_kw_bprep(const float* __restrict__ IF,
                                                  const float* __restrict__ Wval,
                                                  const float* __restrict__ bval) {
    if (blockIdx.x < 128) {
        int h = blockIdx.x >> 4, qb = blockIdx.x & 15;
        int lq0 = qb * 64;
        __shared__ float ws[16][64];
        __shared__ int   is[16][64];
        int tid = threadIdx.x;
        for (int i = tid; i < 1024; i += 256) {
            int s = i >> 6, qq = i & 63;
            ws[s][qq] = g_logits[(size_t)h * NLOG * LQ + (size_t)s * LQ + lq0 + qq];
            is[s][qq] = g_fidx[(h * 16 + s) * LQ + lq0 + qq];
        }
        __syncthreads();
        int qi = tid >> 2, dc = (tid & 3) << 6;
        float4 acc[16];
#pragma unroll
        for (int r = 0; r < 16; r++) acc[r] = make_float4(0.f, 0.f, 0.f, 0.f);
        for (int s = 0; s < 16; s++) {
            float w = ws[s][qi];
            const float4* row = (const float4*)(IF + (size_t)is[s][qi] * CD + dc);
#pragma unroll
            for (int r = 0; r < 16; r++) {
                float4 kv = row[r];
                acc[r].x = fmaf(w, kv.x, acc[r].x);
                acc[r].y = fmaf(w, kv.y, acc[r].y);
                acc[r].z = fmaf(w, kv.z, acc[r].z);
                acc[r].w = fmaf(w, kv.w, acc[r].w);
            }
        }
        float4* out = (float4*)(g_A + (size_t)(lq0 + qi) * KTOT + h * SEG + dc);
#pragma unroll
        for (int r = 0; r < 16; r++) out[r] = acc[r];
    } else {
        int k = blockIdx.x - 128;           // 0..KTOT-1
        int c = threadIdx.x;
        int h = k / SEG, r = k - h * SEG;
        float hw = g_hw[h * CD + c];
        float val;
        if (r < 256)       val = hw * Wval[((size_t)(2 * h) * CD + c) * CD + r];
        else if (r < 512)  val = hw * g_v2[((size_t)h * CD + (r - 256)) * CD + c];
        else if (r == 512) val = hw * bval[(2 * h) * CD + c];
        else               val = 0.f;
        g_B[(size_t)k * CD + c] = val;
    }
}

// fused output GEMM per (head, K-half) -> per-(head,half) partials
__global__ void __launch_bounds__(256, 2) k_fused() {
    int h = blockIdx.x >> 5;
    int sub = blockIdx.x & 31;
    int mt = sub & 15, half = sub >> 4;
    int koff = half ? KH0 : 0;
    int K    = half ? KH1 : KH0;
    gemm_64x256<1>(g_A + (size_t)mt * 64 * KTOT + h * SEG + koff, KTOT,
                   g_B + ((size_t)h * SEG + koff) * CD, CD, nullptr, nullptr,
                   K,
                   g_Cpart + (((size_t)(h * 2 + half) * LQ) + mt * 64) * CD, CD, nullptr);
}

__global__ void __launch_bounds__(256) k_out(const float* __restrict__ q,
                                             float* __restrict__ out) {
    int e = blockIdx.x * 256 + threadIdx.x;     // 65536 float4
    int c4 = e & 63;
    float4 qv = ((const float4*)q)[e];
    float4 hw = ((const float4*)(g_hw + 8 * CD))[c4];
    float4 r;
    r.x = qv.x * hw.x; r.y = qv.y * hw.y; r.z = qv.z * hw.z; r.w = qv.w * hw.w;
#pragma unroll
    for (int hp = 0; hp < NH * 2; hp++) {
        float4 p = ((const float4*)(g_Cpart + (size_t)hp * LQ * CD))[e];
        r.x += p.x; r.y += p.y; r.z += p.z; r.w += p.w;
    }
    ((float4*)out)[e] = r;
}

extern "C" void kernel_launch(void* const* d_in, const int* in_sizes, int n_in,
                              void* d_out, int out_size) {
    const float* query  = (const float*)d_in[0];
    const float* refp   = (const float*)d_in[1];
    const float* IF     = (const float*)d_in[2];
    const int*   iss    = (const int*)d_in[3];
    const float* addk   = (const float*)d_in[4];
    const int*   lstart = (const int*)d_in[5];
    const float* Woff   = (const float*)d_in[6];
    const float* boff   = (const float*)d_in[7];
    const float* Wattn  = (const float*)d_in[8];
    const float* Wval   = (const float*)d_in[9];
    const float* bval   = (const float*)d_in[10];
    const float* Wmix   = (const float*)d_in[11];
    float* out = (float*)d_out;

    k_off_hw<<<17, 256>>>(query, Woff, boff, Wmix);
    k_idx<<<512, 256>>>(refp, iss, lstart);
    k_T_a2v2<<<576, 256>>>(query, IF, addk, Wattn, Wval, bval);
    k_logits<<<384, 256>>>(Wattn, query);
    k_softmax<<<1024, 256>>>();
    k_kw_bprep<<<128 + KTOT, 256>>>(IF, Wval, bval);
    k_fused<<<256, 256>>>();
    k_out<<<256, 256>>>(query, out);
}